// round 11
// baseline (speedup 1.0000x reference)
#include <cuda_runtime.h>
#include <cstdint>

#define IMH 256
#define IMW 256

// 402 MB scratch for hidden = conv1x1(x) + b_hidden, NCHW [4][384][256][256]
__device__ float g_hidden[4 * 384 * 256 * 256];

// ======================= K1: 1x1 conv, whole image, no halo =======================
// grid (512, 4): 512 strips of 128 contiguous pixels per batch.
// 512 threads, 2 CTAs/SM (2*512*64 = 64K regs -> no spills).
// thread = 4 pixels x 8 channels; double-buffered weight staging.
#define K1_SMEM (64 * 128 + 2 * 64 * 132)   // 25088 floats = 100352 B

extern __shared__ float smem[];

__global__ __launch_bounds__(512, 2)
void k1_conv1x1(const float* __restrict__ x,
                const float* __restrict__ w_hidden,
                const float* __restrict__ b_hidden)
{
    float* xs = smem;                       // [64][128]
    float* wsbuf[2] = { smem + 8192, smem + 8192 + 8448 };

    const int t   = threadIdx.x;
    const int b   = blockIdx.y;
    const int px0 = blockIdx.x * 128;
    const int pxg = t >> 4;        // 0..31: pixels pxg*4..pxg*4+3
    const int chg = t & 15;        // 0..15: channels chg*8..chg*8+7 (of 128/pass)

    // stage x strip: xs[c][p] (coalesced)
    for (int idx = t; idx < 64 * 128; idx += 512) {
        int c = idx >> 7, p = idx & 127;
        xs[idx] = x[((size_t)(b * 64 + c) << 16) + px0 + p];
    }
    // stage pass-0 weights
    for (int idx = t; idx < 64 * 128; idx += 512) {
        int i = idx & 63, c = idx >> 6;
        wsbuf[0][i * 132 + c] = w_hidden[c * 64 + i];
    }
    __syncthreads();

    for (int pass = 0; pass < 3; ++pass) {
        const int pch = pass * 128;
        const float* ws = wsbuf[pass & 1];

        // prefetch next pass's weights into the idle buffer
        if (pass < 2) {
            float* wn = wsbuf[(pass + 1) & 1];
            for (int idx = t; idx < 64 * 128; idx += 512) {
                int i = idx & 63, c = idx >> 6;
                wn[i * 132 + c] = w_hidden[(pch + 128 + c) * 64 + i];
            }
        }

        float acc[8][4];
        #pragma unroll
        for (int j = 0; j < 8; ++j) {
            float bv = __ldg(&b_hidden[pch + chg * 8 + j]);
            acc[j][0] = bv; acc[j][1] = bv; acc[j][2] = bv; acc[j][3] = bv;
        }
        const float* xsp = xs + pxg * 4;
        const float* wsp = ws + chg * 8;
        #pragma unroll 4
        for (int i = 0; i < 64; ++i) {
            float4 xv = *(const float4*)(xsp + i * 128);
            float4 w0 = *(const float4*)(wsp + i * 132);
            float4 w1 = *(const float4*)(wsp + i * 132 + 4);
            float wv[8] = {w0.x, w0.y, w0.z, w0.w, w1.x, w1.y, w1.z, w1.w};
            #pragma unroll
            for (int j = 0; j < 8; ++j) {
                acc[j][0] += wv[j] * xv.x;
                acc[j][1] += wv[j] * xv.y;
                acc[j][2] += wv[j] * xv.z;
                acc[j][3] += wv[j] * xv.w;
            }
        }

        #pragma unroll
        for (int j = 0; j < 8; ++j) {
            int c = pch + chg * 8 + j;
            float4 hv = make_float4(acc[j][0], acc[j][1], acc[j][2], acc[j][3]);
            *(float4*)(g_hidden + ((size_t)(b * 384 + c) << 16) + px0 + pxg * 4) = hv;
        }
        __syncthreads();   // next-pass weights visible; this pass's ws reads done
    }
}

// ======================= K2: dw conv + circ-conv + LN + proj =======================
// grid (32, 32, 4): one 8x8 patch per block. 1024 threads. (unchanged from R10)
#define OFF_HS   0          // hs [128][120] = 15360; wpT[128][68] overlays after passes
#define OFF_WPT  0
#define OFF_Q    15360      // [128][68]
#define OFF_K    24064      // [128][68]
#define OFF_V    32768      // [128][68]  (also proj partial scratch, 4096 floats)
#define OFF_PS   41472      // [16][66]
#define OFF_PQ   42528      // [16][66]
#define OFF_MEAN 43584      // [64]
#define OFF_RSTD 43648      // [64]
#define K2_SMEM  43712      // 174848 bytes

__global__ __launch_bounds__(1024, 1)
void k2_rest(const float* __restrict__ w_dw,
             const float* __restrict__ b_dw,
             const float* __restrict__ w_proj,
             const float* __restrict__ b_proj,
             const float* __restrict__ ln_w,
             const float* __restrict__ ln_b,
             float* __restrict__ out)
{
    float* hs   = smem + OFF_HS;
    float* wpT  = smem + OFF_WPT;
    float* qsm  = smem + OFF_Q;
    float* ksm  = smem + OFF_K;
    float* vsm  = smem + OFF_V;
    float* ps   = smem + OFF_PS;
    float* pq   = smem + OFF_PQ;
    float* mean_s = smem + OFF_MEAN;
    float* rstd_s = smem + OFF_RSTD;

    const int t  = threadIdx.x;
    const int bx = blockIdx.x;
    const int by = blockIdx.y;
    const int bb = blockIdx.z;
    const int gx0 = bx * 8 - 1;
    const int gy0 = by * 8 - 1;

    const int c   = t >> 3;       // 0..127 (dw / B / LN-apply channel)
    const int row = t & 7;        // 0..7
    const int p8  = t & 63;
    const int i8  = p8 >> 3;
    const int j8  = p8 & 7;
    const int clg = t >> 6;       // 0..15

    // ---- staging geometry: tp = t&127 is the SAME tile pixel for all 16 of
    // this thread's loads (1024 stride ≡ 0 mod 128); channels cc0 + 8u.
    const int tp  = t & 127;
    const int cc0 = t >> 7;       // 0..7
    int sty = tp / 10, stx = tp - sty * 10;
    const int sgy = gy0 + sty, sgx = gx0 + stx;
    const bool sload = (tp < 100) && ((unsigned)sgy < IMH) && ((unsigned)sgx < IMW);
    const bool sstore = (tp < 100);
    const size_t gpix = ((size_t)sgy << 8) + sgx;
    const int hoff = sty * 12 + stx;

    // prefetch pass-0 hidden (batched independent loads -> MLP=16)
    float v[16];
    {
        const float* gbase = g_hidden + (((size_t)(bb * 384 + cc0)) << 16) + gpix;
        #pragma unroll
        for (int u = 0; u < 16; ++u)
            v[u] = sload ? __ldg(gbase + ((size_t)(8 * u) << 16)) : 0.f;
    }

    // ---- 3 passes: store staged tile + prefetch next + depthwise 3x3 ----
    for (int pass = 0; pass < 3; ++pass) {
        const int pch = pass * 128;

        __syncthreads();   // hs free (prev dw done)
        if (sstore) {
            #pragma unroll
            for (int u = 0; u < 16; ++u)
                hs[(cc0 + 8 * u) * 120 + hoff] = v[u];
        }
        __syncthreads();

        // prefetch next pass's hidden; latency hides behind the dw conv below
        if (pass < 2) {
            const float* gbase = g_hidden + (((size_t)(bb * 384 + pch + 128 + cc0)) << 16) + gpix;
            #pragma unroll
            for (int u = 0; u < 16; ++u)
                v[u] = sload ? __ldg(gbase + ((size_t)(8 * u) << 16)) : 0.f;
        }

        float* dst = (pass == 0) ? qsm : (pass == 1) ? ksm : vsm;
        float wd9[9];
        #pragma unroll
        for (int tap = 0; tap < 9; ++tap) wd9[tap] = __ldg(&w_dw[(pch + c) * 9 + tap]);
        float bv = __ldg(&b_dw[pch + c]);
        float o8[8];
        #pragma unroll
        for (int j = 0; j < 8; ++j) o8[j] = bv;
        const float* hrow = hs + c * 120 + row * 12;
        #pragma unroll
        for (int dy = 0; dy < 3; ++dy) {
            float4 A0 = *(const float4*)(hrow + dy * 12);
            float4 A1 = *(const float4*)(hrow + dy * 12 + 4);
            float4 A2 = *(const float4*)(hrow + dy * 12 + 8);
            float rr[12] = {A0.x, A0.y, A0.z, A0.w, A1.x, A1.y, A1.z, A1.w,
                            A2.x, A2.y, A2.z, A2.w};
            float w0 = wd9[dy * 3], w1 = wd9[dy * 3 + 1], w2 = wd9[dy * 3 + 2];
            #pragma unroll
            for (int j = 0; j < 8; ++j)
                o8[j] += rr[j] * w0 + rr[j + 1] * w1 + rr[j + 2] * w2;
        }
        *(float4*)(dst + c * 68 + row * 8)     = make_float4(o8[0], o8[1], o8[2], o8[3]);
        *(float4*)(dst + c * 68 + row * 8 + 4) = make_float4(o8[4], o8[5], o8[6], o8[7]);
    }
    __syncthreads();   // dw done with hs -> overlay wpT

    // stage wpT[c][68] = w_proj[o][c]
    for (int idx = t; idx < 64 * 128; idx += 1024) {
        int cc = idx & 127, o = idx >> 7;
        wpT[cc * 68 + o] = w_proj[o * 128 + cc];
    }
    // ordered before proj by the syncs below

    // ---- Phase B: circular conv per 8x8 patch ----
    float bacc[8];
    #pragma unroll
    for (int j = 0; j < 8; ++j) bacc[j] = 0.f;
    {
        const float* qrow = qsm + c * 68;
        const float* krow = ksm + c * 68;
        #pragma unroll
        for (int a = 0; a < 8; ++a) {
            float4 qa = *(const float4*)(qrow + a * 8);
            float4 qb = *(const float4*)(qrow + a * 8 + 4);
            float qq[8] = {qa.x, qa.y, qa.z, qa.w, qb.x, qb.y, qb.z, qb.w};
            int r0 = (row - a) & 7;
            float4 k0 = *(const float4*)(krow + r0 * 8);
            float4 k1 = *(const float4*)(krow + r0 * 8 + 4);
            float kk[8] = {k0.x, k0.y, k0.z, k0.w, k1.x, k1.y, k1.z, k1.w};
            #pragma unroll
            for (int b2 = 0; b2 < 8; ++b2) {
                #pragma unroll
                for (int j = 0; j < 8; ++j)
                    bacc[j] += qq[b2] * kk[(j - b2) & 7];
            }
        }
    }
    __syncthreads();

    // write Phase-B output to qsm (q dead) for the LN reduction
    *(float4*)(qsm + c * 68 + row * 8)     = make_float4(bacc[0], bacc[1], bacc[2], bacc[3]);
    *(float4*)(qsm + c * 68 + row * 8 + 4) = make_float4(bacc[4], bacc[5], bacc[6], bacc[7]);
    __syncthreads();

    // ---- LayerNorm stats over 128 channels per pixel ----
    {
        float s = 0.f, ss = 0.f;
        #pragma unroll
        for (int u = 0; u < 8; ++u) {
            float v2 = qsm[(clg * 8 + u) * 68 + p8];
            s += v2; ss += v2 * v2;
        }
        ps[clg * 66 + p8] = s;
        pq[clg * 66 + p8] = ss;
    }
    __syncthreads();
    if (t < 64) {
        float sm = 0.f, sq = 0.f;
        #pragma unroll
        for (int g = 0; g < 16; ++g) { sm += ps[g * 66 + t]; sq += pq[g * 66 + t]; }
        float mu  = sm * (1.f / 128.f);
        float var = sq * (1.f / 128.f) - mu * mu;
        mean_s[t] = mu;
        rstd_s[t] = rsqrtf(var + 1e-5f);
    }
    __syncthreads();

    // ---- normalize, scale/shift, multiply by v -> ksm (k dead) ----
    {
        float lw = __ldg(&ln_w[c]);
        float lb = __ldg(&ln_b[c]);
        float4 v0 = *(const float4*)(vsm + c * 68 + row * 8);
        float4 v1 = *(const float4*)(vsm + c * 68 + row * 8 + 4);
        float vv[8] = {v0.x, v0.y, v0.z, v0.w, v1.x, v1.y, v1.z, v1.w};
        float ov[8];
        #pragma unroll
        for (int j = 0; j < 8; ++j) {
            int px = row * 8 + j;
            float o = (bacc[j] - mean_s[px]) * rstd_s[px] * lw + lb;
            ov[j] = vv[j] * o;
        }
        *(float4*)(ksm + c * 68 + row * 8)     = make_float4(ov[0], ov[1], ov[2], ov[3]);
        *(float4*)(ksm + c * 68 + row * 8 + 4) = make_float4(ov[4], ov[5], ov[6], ov[7]);
    }
    __syncthreads();

    // ---- 1x1 projection 128 -> 64, split-K over 2 channel halves ----
    {
        const int ppx   = t & 63;         // pixel
        const int pog   = (t >> 6) & 7;   // outputs pog*8..pog*8+7
        const int phalf = t >> 9;         // 0 or 1: cc in [phalf*64, phalf*64+64)
        float r[8];
        #pragma unroll
        for (int j = 0; j < 8; ++j)
            r[j] = phalf ? 0.f : __ldg(&b_proj[pog * 8 + j]);

        const int ccb = phalf * 64;
        #pragma unroll 8
        for (int cc = ccb; cc < ccb + 64; ++cc) {
            float ov = ksm[cc * 68 + ppx];
            float4 w0 = *(const float4*)(wpT + cc * 68 + pog * 8);
            float4 w1 = *(const float4*)(wpT + cc * 68 + pog * 8 + 4);
            r[0] += ov * w0.x;  r[1] += ov * w0.y;
            r[2] += ov * w0.z;  r[3] += ov * w0.w;
            r[4] += ov * w1.x;  r[5] += ov * w1.y;
            r[6] += ov * w1.z;  r[7] += ov * w1.w;
        }

        // half-1 threads write partials into vsm scratch (vsm dead after LN-apply)
        if (phalf) {
            int s = (t - 512) * 8;
            *(float4*)(vsm + s)     = make_float4(r[0], r[1], r[2], r[3]);
            *(float4*)(vsm + s + 4) = make_float4(r[4], r[5], r[6], r[7]);
        }
        __syncthreads();
        if (!phalf) {
            float4 p0 = *(const float4*)(vsm + t * 8);
            float4 p1 = *(const float4*)(vsm + t * 8 + 4);
            r[0] += p0.x; r[1] += p0.y; r[2] += p0.z; r[3] += p0.w;
            r[4] += p1.x; r[5] += p1.y; r[6] += p1.z; r[7] += p1.w;

            const int gy = by * 8 + i8;
            const int gx = bx * 8 + j8;
            #pragma unroll
            for (int j = 0; j < 8; ++j) {
                int o = pog * 8 + j;
                out[((size_t)(bb * 64 + o) * IMH + gy) * IMW + gx] = r[j];
            }
        }
    }
}

extern "C" void kernel_launch(void* const* d_in, const int* in_sizes, int n_in,
                              void* d_out, int out_size) {
    const float* x        = (const float*)d_in[0];
    const float* w_hidden = (const float*)d_in[1];
    const float* b_hidden = (const float*)d_in[2];
    const float* w_dw     = (const float*)d_in[3];
    const float* b_dw     = (const float*)d_in[4];
    const float* w_proj   = (const float*)d_in[5];
    const float* b_proj   = (const float*)d_in[6];
    const float* ln_w     = (const float*)d_in[7];
    const float* ln_b     = (const float*)d_in[8];
    float* out = (float*)d_out;

    const int k1_smem = K1_SMEM * sizeof(float);   // 100352 B
    const int k2_smem = K2_SMEM * sizeof(float);   // 174848 B
    cudaFuncSetAttribute(k1_conv1x1, cudaFuncAttributeMaxDynamicSharedMemorySize, k1_smem);
    cudaFuncSetAttribute(k2_rest,    cudaFuncAttributeMaxDynamicSharedMemorySize, k2_smem);

    dim3 g1(512, 4);
    k1_conv1x1<<<g1, 512, k1_smem>>>(x, w_hidden, b_hidden);

    dim3 g2(32, 32, 4);
    k2_rest<<<g2, 1024, k2_smem>>>(w_dw, b_dw, w_proj, b_proj, ln_w, ln_b, out);
}

// round 12
// speedup vs baseline: 1.0870x; 1.0870x over previous
#include <cuda_runtime.h>
#include <cstdint>

#define IMH 256
#define IMW 256

// 402 MB scratch for hidden = conv1x1(x) + b_hidden, NCHW [4][384][256][256]
__device__ float g_hidden[4 * 384 * 256 * 256];

// ======================= K1: 1x1 conv, whole image, no halo =======================
// grid (512, 4): 512 strips of 128 contiguous pixels per batch.
// 1024 threads, 1 CTA/SM. warp = 4 pixels (broadcast x), lane = 4 channels.
// double-buffered weight staging: one barrier per pass.
#define K1_SMEM (64 * 128 + 2 * 64 * 132)   // 25088 floats = 100352 B

extern __shared__ float smem[];

__global__ __launch_bounds__(1024, 1)
void k1_conv1x1(const float* __restrict__ x,
                const float* __restrict__ w_hidden,
                const float* __restrict__ b_hidden)
{
    float* xs = smem;                       // [64][128]
    float* wsbuf[2] = { smem + 8192, smem + 8192 + 8448 };

    const int t   = threadIdx.x;
    const int b   = blockIdx.y;
    const int px0 = blockIdx.x * 128;
    const int w   = t >> 5;        // warp: pixels w*4..w*4+3
    const int l   = t & 31;        // lane: channels l*4..l*4+3

    // stage x strip: xs[c][p] (coalesced)
    for (int idx = t; idx < 64 * 128; idx += 1024) {
        int c = idx >> 7, p = idx & 127;
        xs[idx] = x[((size_t)(b * 64 + c) << 16) + px0 + p];
    }
    // stage pass-0 weights
    for (int idx = t; idx < 64 * 128; idx += 1024) {
        int i = idx & 63, c = idx >> 6;
        wsbuf[0][i * 132 + c] = w_hidden[c * 64 + i];
    }
    __syncthreads();

    for (int pass = 0; pass < 3; ++pass) {
        const int pch = pass * 128;
        const float* ws = wsbuf[pass & 1];

        // prefetch next pass's weights into the idle buffer (its readers
        // finished before the barrier that ended the previous pass)
        if (pass < 2) {
            float* wn = wsbuf[(pass + 1) & 1];
            for (int idx = t; idx < 64 * 128; idx += 1024) {
                int i = idx & 63, c = idx >> 6;
                wn[i * 132 + c] = w_hidden[(pch + 128 + c) * 64 + i];
            }
        }

        float acc[4][4];
        #pragma unroll
        for (int j = 0; j < 4; ++j) {
            float bv = __ldg(&b_hidden[pch + l * 4 + j]);
            acc[j][0] = bv; acc[j][1] = bv; acc[j][2] = bv; acc[j][3] = bv;
        }
        const float* xsp = xs + w * 4;
        const float* wsp = ws + l * 4;
        #pragma unroll 4
        for (int i = 0; i < 64; ++i) {
            float4 xv = *(const float4*)(xsp + i * 128);
            float4 wv = *(const float4*)(wsp + i * 132);
            acc[0][0] += wv.x * xv.x; acc[0][1] += wv.x * xv.y;
            acc[0][2] += wv.x * xv.z; acc[0][3] += wv.x * xv.w;
            acc[1][0] += wv.y * xv.x; acc[1][1] += wv.y * xv.y;
            acc[1][2] += wv.y * xv.z; acc[1][3] += wv.y * xv.w;
            acc[2][0] += wv.z * xv.x; acc[2][1] += wv.z * xv.y;
            acc[2][2] += wv.z * xv.z; acc[2][3] += wv.z * xv.w;
            acc[3][0] += wv.w * xv.x; acc[3][1] += wv.w * xv.y;
            acc[3][2] += wv.w * xv.z; acc[3][3] += wv.w * xv.w;
        }

        #pragma unroll
        for (int j = 0; j < 4; ++j) {
            int c = pch + l * 4 + j;
            float4 hv = make_float4(acc[j][0], acc[j][1], acc[j][2], acc[j][3]);
            *(float4*)(g_hidden + ((size_t)(b * 384 + c) << 16) + px0 + w * 4) = hv;
        }
        __syncthreads();   // next-pass weights visible; this pass's ws reads done
    }
}

// ======================= K2: dw conv + circ-conv + LN + proj =======================
// grid (32, 32, 4): one 8x8 patch per block. 1024 threads. (unchanged, 604us verified)
#define OFF_HS   0          // hs [128][120] = 15360; wpT[128][68] overlays after passes
#define OFF_WPT  0
#define OFF_Q    15360      // [128][68]
#define OFF_K    24064      // [128][68]
#define OFF_V    32768      // [128][68]  (also proj partial scratch, 4096 floats)
#define OFF_PS   41472      // [16][66]
#define OFF_PQ   42528      // [16][66]
#define OFF_MEAN 43584      // [64]
#define OFF_RSTD 43648      // [64]
#define K2_SMEM  43712      // 174848 bytes

__global__ __launch_bounds__(1024, 1)
void k2_rest(const float* __restrict__ w_dw,
             const float* __restrict__ b_dw,
             const float* __restrict__ w_proj,
             const float* __restrict__ b_proj,
             const float* __restrict__ ln_w,
             const float* __restrict__ ln_b,
             float* __restrict__ out)
{
    float* hs   = smem + OFF_HS;
    float* wpT  = smem + OFF_WPT;
    float* qsm  = smem + OFF_Q;
    float* ksm  = smem + OFF_K;
    float* vsm  = smem + OFF_V;
    float* ps   = smem + OFF_PS;
    float* pq   = smem + OFF_PQ;
    float* mean_s = smem + OFF_MEAN;
    float* rstd_s = smem + OFF_RSTD;

    const int t  = threadIdx.x;
    const int bx = blockIdx.x;
    const int by = blockIdx.y;
    const int bb = blockIdx.z;
    const int gx0 = bx * 8 - 1;
    const int gy0 = by * 8 - 1;

    const int c   = t >> 3;       // 0..127 (dw / B / LN-apply channel)
    const int row = t & 7;        // 0..7
    const int p8  = t & 63;
    const int i8  = p8 >> 3;
    const int j8  = p8 & 7;
    const int clg = t >> 6;       // 0..15

    // ---- staging geometry: tp = t&127 is the SAME tile pixel for all 16 of
    // this thread's loads (1024 stride ≡ 0 mod 128); channels cc0 + 8u.
    const int tp  = t & 127;
    const int cc0 = t >> 7;       // 0..7
    int sty = tp / 10, stx = tp - sty * 10;
    const int sgy = gy0 + sty, sgx = gx0 + stx;
    const bool sload = (tp < 100) && ((unsigned)sgy < IMH) && ((unsigned)sgx < IMW);
    const bool sstore = (tp < 100);
    const size_t gpix = ((size_t)sgy << 8) + sgx;
    const int hoff = sty * 12 + stx;

    // prefetch pass-0 hidden (batched independent loads -> MLP=16)
    float v[16];
    {
        const float* gbase = g_hidden + (((size_t)(bb * 384 + cc0)) << 16) + gpix;
        #pragma unroll
        for (int u = 0; u < 16; ++u)
            v[u] = sload ? __ldg(gbase + ((size_t)(8 * u) << 16)) : 0.f;
    }

    // ---- 3 passes: store staged tile + prefetch next + depthwise 3x3 ----
    for (int pass = 0; pass < 3; ++pass) {
        const int pch = pass * 128;

        __syncthreads();   // hs free (prev dw done)
        if (sstore) {
            #pragma unroll
            for (int u = 0; u < 16; ++u)
                hs[(cc0 + 8 * u) * 120 + hoff] = v[u];
        }
        __syncthreads();

        // prefetch next pass's hidden; latency hides behind the dw conv below
        if (pass < 2) {
            const float* gbase = g_hidden + (((size_t)(bb * 384 + pch + 128 + cc0)) << 16) + gpix;
            #pragma unroll
            for (int u = 0; u < 16; ++u)
                v[u] = sload ? __ldg(gbase + ((size_t)(8 * u) << 16)) : 0.f;
        }

        float* dst = (pass == 0) ? qsm : (pass == 1) ? ksm : vsm;
        float wd9[9];
        #pragma unroll
        for (int tap = 0; tap < 9; ++tap) wd9[tap] = __ldg(&w_dw[(pch + c) * 9 + tap]);
        float bv = __ldg(&b_dw[pch + c]);
        float o8[8];
        #pragma unroll
        for (int j = 0; j < 8; ++j) o8[j] = bv;
        const float* hrow = hs + c * 120 + row * 12;
        #pragma unroll
        for (int dy = 0; dy < 3; ++dy) {
            float4 A0 = *(const float4*)(hrow + dy * 12);
            float4 A1 = *(const float4*)(hrow + dy * 12 + 4);
            float4 A2 = *(const float4*)(hrow + dy * 12 + 8);
            float rr[12] = {A0.x, A0.y, A0.z, A0.w, A1.x, A1.y, A1.z, A1.w,
                            A2.x, A2.y, A2.z, A2.w};
            float w0 = wd9[dy * 3], w1 = wd9[dy * 3 + 1], w2 = wd9[dy * 3 + 2];
            #pragma unroll
            for (int j = 0; j < 8; ++j)
                o8[j] += rr[j] * w0 + rr[j + 1] * w1 + rr[j + 2] * w2;
        }
        *(float4*)(dst + c * 68 + row * 8)     = make_float4(o8[0], o8[1], o8[2], o8[3]);
        *(float4*)(dst + c * 68 + row * 8 + 4) = make_float4(o8[4], o8[5], o8[6], o8[7]);
    }
    __syncthreads();   // dw done with hs -> overlay wpT

    // stage wpT[c][68] = w_proj[o][c]
    for (int idx = t; idx < 64 * 128; idx += 1024) {
        int cc = idx & 127, o = idx >> 7;
        wpT[cc * 68 + o] = w_proj[o * 128 + cc];
    }
    // ordered before proj by the syncs below

    // ---- Phase B: circular conv per 8x8 patch ----
    float bacc[8];
    #pragma unroll
    for (int j = 0; j < 8; ++j) bacc[j] = 0.f;
    {
        const float* qrow = qsm + c * 68;
        const float* krow = ksm + c * 68;
        #pragma unroll
        for (int a = 0; a < 8; ++a) {
            float4 qa = *(const float4*)(qrow + a * 8);
            float4 qb = *(const float4*)(qrow + a * 8 + 4);
            float qq[8] = {qa.x, qa.y, qa.z, qa.w, qb.x, qb.y, qb.z, qb.w};
            int r0 = (row - a) & 7;
            float4 k0 = *(const float4*)(krow + r0 * 8);
            float4 k1 = *(const float4*)(krow + r0 * 8 + 4);
            float kk[8] = {k0.x, k0.y, k0.z, k0.w, k1.x, k1.y, k1.z, k1.w};
            #pragma unroll
            for (int b2 = 0; b2 < 8; ++b2) {
                #pragma unroll
                for (int j = 0; j < 8; ++j)
                    bacc[j] += qq[b2] * kk[(j - b2) & 7];
            }
        }
    }
    __syncthreads();

    // write Phase-B output to qsm (q dead) for the LN reduction
    *(float4*)(qsm + c * 68 + row * 8)     = make_float4(bacc[0], bacc[1], bacc[2], bacc[3]);
    *(float4*)(qsm + c * 68 + row * 8 + 4) = make_float4(bacc[4], bacc[5], bacc[6], bacc[7]);
    __syncthreads();

    // ---- LayerNorm stats over 128 channels per pixel ----
    {
        float s = 0.f, ss = 0.f;
        #pragma unroll
        for (int u = 0; u < 8; ++u) {
            float v2 = qsm[(clg * 8 + u) * 68 + p8];
            s += v2; ss += v2 * v2;
        }
        ps[clg * 66 + p8] = s;
        pq[clg * 66 + p8] = ss;
    }
    __syncthreads();
    if (t < 64) {
        float sm = 0.f, sq = 0.f;
        #pragma unroll
        for (int g = 0; g < 16; ++g) { sm += ps[g * 66 + t]; sq += pq[g * 66 + t]; }
        float mu  = sm * (1.f / 128.f);
        float var = sq * (1.f / 128.f) - mu * mu;
        mean_s[t] = mu;
        rstd_s[t] = rsqrtf(var + 1e-5f);
    }
    __syncthreads();

    // ---- normalize, scale/shift, multiply by v -> ksm (k dead) ----
    {
        float lw = __ldg(&ln_w[c]);
        float lb = __ldg(&ln_b[c]);
        float4 v0 = *(const float4*)(vsm + c * 68 + row * 8);
        float4 v1 = *(const float4*)(vsm + c * 68 + row * 8 + 4);
        float vv[8] = {v0.x, v0.y, v0.z, v0.w, v1.x, v1.y, v1.z, v1.w};
        float ov[8];
        #pragma unroll
        for (int j = 0; j < 8; ++j) {
            int px = row * 8 + j;
            float o = (bacc[j] - mean_s[px]) * rstd_s[px] * lw + lb;
            ov[j] = vv[j] * o;
        }
        *(float4*)(ksm + c * 68 + row * 8)     = make_float4(ov[0], ov[1], ov[2], ov[3]);
        *(float4*)(ksm + c * 68 + row * 8 + 4) = make_float4(ov[4], ov[5], ov[6], ov[7]);
    }
    __syncthreads();

    // ---- 1x1 projection 128 -> 64, split-K over 2 channel halves ----
    {
        const int ppx   = t & 63;         // pixel
        const int pog   = (t >> 6) & 7;   // outputs pog*8..pog*8+7
        const int phalf = t >> 9;         // 0 or 1: cc in [phalf*64, phalf*64+64)
        float r[8];
        #pragma unroll
        for (int j = 0; j < 8; ++j)
            r[j] = phalf ? 0.f : __ldg(&b_proj[pog * 8 + j]);

        const int ccb = phalf * 64;
        #pragma unroll 8
        for (int cc = ccb; cc < ccb + 64; ++cc) {
            float ov = ksm[cc * 68 + ppx];
            float4 w0 = *(const float4*)(wpT + cc * 68 + pog * 8);
            float4 w1 = *(const float4*)(wpT + cc * 68 + pog * 8 + 4);
            r[0] += ov * w0.x;  r[1] += ov * w0.y;
            r[2] += ov * w0.z;  r[3] += ov * w0.w;
            r[4] += ov * w1.x;  r[5] += ov * w1.y;
            r[6] += ov * w1.z;  r[7] += ov * w1.w;
        }

        // half-1 threads write partials into vsm scratch (vsm dead after LN-apply)
        if (phalf) {
            int s = (t - 512) * 8;
            *(float4*)(vsm + s)     = make_float4(r[0], r[1], r[2], r[3]);
            *(float4*)(vsm + s + 4) = make_float4(r[4], r[5], r[6], r[7]);
        }
        __syncthreads();
        if (!phalf) {
            float4 p0 = *(const float4*)(vsm + t * 8);
            float4 p1 = *(const float4*)(vsm + t * 8 + 4);
            r[0] += p0.x; r[1] += p0.y; r[2] += p0.z; r[3] += p0.w;
            r[4] += p1.x; r[5] += p1.y; r[6] += p1.z; r[7] += p1.w;

            const int gy = by * 8 + i8;
            const int gx = bx * 8 + j8;
            #pragma unroll
            for (int j = 0; j < 8; ++j) {
                int o = pog * 8 + j;
                out[((size_t)(bb * 64 + o) * IMH + gy) * IMW + gx] = r[j];
            }
        }
    }
}

extern "C" void kernel_launch(void* const* d_in, const int* in_sizes, int n_in,
                              void* d_out, int out_size) {
    const float* x        = (const float*)d_in[0];
    const float* w_hidden = (const float*)d_in[1];
    const float* b_hidden = (const float*)d_in[2];
    const float* w_dw     = (const float*)d_in[3];
    const float* b_dw     = (const float*)d_in[4];
    const float* w_proj   = (const float*)d_in[5];
    const float* b_proj   = (const float*)d_in[6];
    const float* ln_w     = (const float*)d_in[7];
    const float* ln_b     = (const float*)d_in[8];
    float* out = (float*)d_out;

    const int k1_smem = K1_SMEM * sizeof(float);   // 100352 B
    const int k2_smem = K2_SMEM * sizeof(float);   // 174848 B
    cudaFuncSetAttribute(k1_conv1x1, cudaFuncAttributeMaxDynamicSharedMemorySize, k1_smem);
    cudaFuncSetAttribute(k2_rest,    cudaFuncAttributeMaxDynamicSharedMemorySize, k2_smem);

    dim3 g1(512, 4);
    k1_conv1x1<<<g1, 1024, k1_smem>>>(x, w_hidden, b_hidden);

    dim3 g2(32, 32, 4);
    k2_rest<<<g2, 1024, k2_smem>>>(w_dw, b_dw, w_proj, b_proj, ln_w, ln_b, out);
}

// round 13
// speedup vs baseline: 1.1269x; 1.0367x over previous
#include <cuda_runtime.h>
#include <cstdint>

#define IMH 256
#define IMW 256

// 402 MB scratch for hidden = conv1x1(x) + b_hidden, NCHW [4][384][256][256]
__device__ float g_hidden[4 * 384 * 256 * 256];

// ======================= K1: 1x1 conv, whole image, no halo =======================
// (unchanged from R12 best: 1024 thr, warp=4px broadcast / lane=4ch, dbuf weights)
#define K1_SMEM (64 * 128 + 2 * 64 * 132)   // 25088 floats = 100352 B

extern __shared__ float smem[];

__global__ __launch_bounds__(1024, 1)
void k1_conv1x1(const float* __restrict__ x,
                const float* __restrict__ w_hidden,
                const float* __restrict__ b_hidden)
{
    float* xs = smem;                       // [64][128]
    float* wsbuf[2] = { smem + 8192, smem + 8192 + 8448 };

    const int t   = threadIdx.x;
    const int b   = blockIdx.y;
    const int px0 = blockIdx.x * 128;
    const int w   = t >> 5;        // warp: pixels w*4..w*4+3
    const int l   = t & 31;        // lane: channels l*4..l*4+3

    for (int idx = t; idx < 64 * 128; idx += 1024) {
        int c = idx >> 7, p = idx & 127;
        xs[idx] = x[((size_t)(b * 64 + c) << 16) + px0 + p];
    }
    for (int idx = t; idx < 64 * 128; idx += 1024) {
        int i = idx & 63, c = idx >> 6;
        wsbuf[0][i * 132 + c] = w_hidden[c * 64 + i];
    }
    __syncthreads();

    for (int pass = 0; pass < 3; ++pass) {
        const int pch = pass * 128;
        const float* ws = wsbuf[pass & 1];

        if (pass < 2) {
            float* wn = wsbuf[(pass + 1) & 1];
            for (int idx = t; idx < 64 * 128; idx += 1024) {
                int i = idx & 63, c = idx >> 6;
                wn[i * 132 + c] = w_hidden[(pch + 128 + c) * 64 + i];
            }
        }

        float acc[4][4];
        #pragma unroll
        for (int j = 0; j < 4; ++j) {
            float bv = __ldg(&b_hidden[pch + l * 4 + j]);
            acc[j][0] = bv; acc[j][1] = bv; acc[j][2] = bv; acc[j][3] = bv;
        }
        const float* xsp = xs + w * 4;
        const float* wsp = ws + l * 4;
        #pragma unroll 4
        for (int i = 0; i < 64; ++i) {
            float4 xv = *(const float4*)(xsp + i * 128);
            float4 wv = *(const float4*)(wsp + i * 132);
            acc[0][0] += wv.x * xv.x; acc[0][1] += wv.x * xv.y;
            acc[0][2] += wv.x * xv.z; acc[0][3] += wv.x * xv.w;
            acc[1][0] += wv.y * xv.x; acc[1][1] += wv.y * xv.y;
            acc[1][2] += wv.y * xv.z; acc[1][3] += wv.y * xv.w;
            acc[2][0] += wv.z * xv.x; acc[2][1] += wv.z * xv.y;
            acc[2][2] += wv.z * xv.z; acc[2][3] += wv.z * xv.w;
            acc[3][0] += wv.w * xv.x; acc[3][1] += wv.w * xv.y;
            acc[3][2] += wv.w * xv.z; acc[3][3] += wv.w * xv.w;
        }

        #pragma unroll
        for (int j = 0; j < 4; ++j) {
            int c = pch + l * 4 + j;
            float4 hv = make_float4(acc[j][0], acc[j][1], acc[j][2], acc[j][3]);
            *(float4*)(g_hidden + ((size_t)(b * 384 + c) << 16) + px0 + w * 4) = hv;
        }
        __syncthreads();
    }
}

// ======================= K2: dw conv + circ-conv + LN + proj =======================
// grid (32, 32, 4): one 8x8 patch per block. 1024 threads.
// Bank-conflict-free thread map: c_lo = t&7, row = (t>>3)&7, c_hi = t>>6.
#define OFF_HS   0          // hs [128][132] = 16896; wpT[128][68] overlays after passes
#define OFF_WPT  0
#define OFF_Q    16896      // [128][68]
#define OFF_K    25600      // [128][68]
#define OFF_V    34304      // [128][68]  (also proj partial scratch, 4096 floats)
#define OFF_PS   43008      // [16][66]
#define OFF_PQ   44064      // [16][66]
#define OFF_MEAN 45120      // [64]
#define OFF_RSTD 45184      // [64]
#define K2_SMEM  45248      // 180992 bytes

__global__ __launch_bounds__(1024, 1)
void k2_rest(const float* __restrict__ w_dw,
             const float* __restrict__ b_dw,
             const float* __restrict__ w_proj,
             const float* __restrict__ b_proj,
             const float* __restrict__ ln_w,
             const float* __restrict__ ln_b,
             float* __restrict__ out)
{
    float* hs   = smem + OFF_HS;
    float* wpT  = smem + OFF_WPT;
    float* qsm  = smem + OFF_Q;
    float* ksm  = smem + OFF_K;
    float* vsm  = smem + OFF_V;
    float* ps   = smem + OFF_PS;
    float* pq   = smem + OFF_PQ;
    float* mean_s = smem + OFF_MEAN;
    float* rstd_s = smem + OFF_RSTD;

    const int t  = threadIdx.x;
    const int bx = blockIdx.x;
    const int by = blockIdx.y;
    const int bb = blockIdx.z;
    const int gx0 = bx * 8 - 1;
    const int gy0 = by * 8 - 1;

    // conflict-free (channel, row) map: quarter-warp = 8 channels, fixed row
    const int c   = ((t >> 6) << 3) | (t & 7);   // 0..127
    const int row = (t >> 3) & 7;                // 0..7
    const int p8  = t & 63;
    const int i8  = p8 >> 3;
    const int j8  = p8 & 7;
    const int clg = t >> 6;       // 0..15 (LN stats map)

    // ---- staging geometry (unchanged): tp = t&127 same pixel for all 16 loads
    const int tp  = t & 127;
    const int cc0 = t >> 7;       // 0..7
    int sty = tp / 10, stx = tp - sty * 10;
    const int sgy = gy0 + sty, sgx = gx0 + stx;
    const bool sload = (tp < 100) && ((unsigned)sgy < IMH) && ((unsigned)sgx < IMW);
    const bool sstore = (tp < 100);
    const size_t gpix = ((size_t)sgy << 8) + sgx;
    const int hoff = sty * 12 + stx;

    // prefetch pass-0 hidden (batched independent loads -> MLP=16)
    float v[16];
    {
        const float* gbase = g_hidden + (((size_t)(bb * 384 + cc0)) << 16) + gpix;
        #pragma unroll
        for (int u = 0; u < 16; ++u)
            v[u] = sload ? __ldg(gbase + ((size_t)(8 * u) << 16)) : 0.f;
    }

    // ---- 3 passes: store staged tile + prefetch next + depthwise 3x3 ----
    for (int pass = 0; pass < 3; ++pass) {
        const int pch = pass * 128;

        __syncthreads();   // hs free (prev dw done)
        if (sstore) {
            #pragma unroll
            for (int u = 0; u < 16; ++u)
                hs[(cc0 + 8 * u) * 132 + hoff] = v[u];
        }
        __syncthreads();

        if (pass < 2) {
            const float* gbase = g_hidden + (((size_t)(bb * 384 + pch + 128 + cc0)) << 16) + gpix;
            #pragma unroll
            for (int u = 0; u < 16; ++u)
                v[u] = sload ? __ldg(gbase + ((size_t)(8 * u) << 16)) : 0.f;
        }

        float* dst = (pass == 0) ? qsm : (pass == 1) ? ksm : vsm;
        float wd9[9];
        #pragma unroll
        for (int tap = 0; tap < 9; ++tap) wd9[tap] = __ldg(&w_dw[(pch + c) * 9 + tap]);
        float bv = __ldg(&b_dw[pch + c]);
        float o8[8];
        #pragma unroll
        for (int j = 0; j < 8; ++j) o8[j] = bv;
        const float* hrow = hs + c * 132 + row * 12;
        #pragma unroll
        for (int dy = 0; dy < 3; ++dy) {
            float4 A0 = *(const float4*)(hrow + dy * 12);
            float4 A1 = *(const float4*)(hrow + dy * 12 + 4);
            float4 A2 = *(const float4*)(hrow + dy * 12 + 8);
            float rr[12] = {A0.x, A0.y, A0.z, A0.w, A1.x, A1.y, A1.z, A1.w,
                            A2.x, A2.y, A2.z, A2.w};
            float w0 = wd9[dy * 3], w1 = wd9[dy * 3 + 1], w2 = wd9[dy * 3 + 2];
            #pragma unroll
            for (int j = 0; j < 8; ++j)
                o8[j] += rr[j] * w0 + rr[j + 1] * w1 + rr[j + 2] * w2;
        }
        *(float4*)(dst + c * 68 + row * 8)     = make_float4(o8[0], o8[1], o8[2], o8[3]);
        *(float4*)(dst + c * 68 + row * 8 + 4) = make_float4(o8[4], o8[5], o8[6], o8[7]);
    }
    __syncthreads();   // dw done with hs -> overlay wpT

    // stage wpT[c][68] = w_proj[o][c]
    for (int idx = t; idx < 64 * 128; idx += 1024) {
        int cc = idx & 127, o = idx >> 7;
        wpT[cc * 68 + o] = w_proj[o * 128 + cc];
    }
    // ordered before proj by the syncs below

    // ---- Phase B: circular conv per 8x8 patch (conflict-free loads) ----
    float bacc[8];
    #pragma unroll
    for (int j = 0; j < 8; ++j) bacc[j] = 0.f;
    {
        const float* qrow = qsm + c * 68;
        const float* krow = ksm + c * 68;
        #pragma unroll
        for (int a = 0; a < 8; ++a) {
            float4 qa = *(const float4*)(qrow + a * 8);
            float4 qb = *(const float4*)(qrow + a * 8 + 4);
            float qq[8] = {qa.x, qa.y, qa.z, qa.w, qb.x, qb.y, qb.z, qb.w};
            int r0 = (row - a) & 7;
            float4 k0 = *(const float4*)(krow + r0 * 8);
            float4 k1 = *(const float4*)(krow + r0 * 8 + 4);
            float kk[8] = {k0.x, k0.y, k0.z, k0.w, k1.x, k1.y, k1.z, k1.w};
            #pragma unroll
            for (int b2 = 0; b2 < 8; ++b2) {
                #pragma unroll
                for (int j = 0; j < 8; ++j)
                    bacc[j] += qq[b2] * kk[(j - b2) & 7];
            }
        }
    }
    __syncthreads();

    // write Phase-B output to qsm (q dead) for the LN reduction
    *(float4*)(qsm + c * 68 + row * 8)     = make_float4(bacc[0], bacc[1], bacc[2], bacc[3]);
    *(float4*)(qsm + c * 68 + row * 8 + 4) = make_float4(bacc[4], bacc[5], bacc[6], bacc[7]);
    __syncthreads();

    // ---- LayerNorm stats over 128 channels per pixel ----
    {
        float s = 0.f, ss = 0.f;
        #pragma unroll
        for (int u = 0; u < 8; ++u) {
            float v2 = qsm[(clg * 8 + u) * 68 + p8];
            s += v2; ss += v2 * v2;
        }
        ps[clg * 66 + p8] = s;
        pq[clg * 66 + p8] = ss;
    }
    __syncthreads();
    if (t < 64) {
        float sm = 0.f, sq = 0.f;
        #pragma unroll
        for (int g = 0; g < 16; ++g) { sm += ps[g * 66 + t]; sq += pq[g * 66 + t]; }
        float mu  = sm * (1.f / 128.f);
        float var = sq * (1.f / 128.f) - mu * mu;
        mean_s[t] = mu;
        rstd_s[t] = rsqrtf(var + 1e-5f);
    }
    __syncthreads();

    // ---- normalize, scale/shift, multiply by v -> ksm (k dead) ----
    {
        float lw = __ldg(&ln_w[c]);
        float lb = __ldg(&ln_b[c]);
        float4 v0 = *(const float4*)(vsm + c * 68 + row * 8);
        float4 v1 = *(const float4*)(vsm + c * 68 + row * 8 + 4);
        float vv[8] = {v0.x, v0.y, v0.z, v0.w, v1.x, v1.y, v1.z, v1.w};
        float ov[8];
        #pragma unroll
        for (int j = 0; j < 8; ++j) {
            int px = row * 8 + j;
            float o = (bacc[j] - mean_s[px]) * rstd_s[px] * lw + lb;
            ov[j] = vv[j] * o;
        }
        *(float4*)(ksm + c * 68 + row * 8)     = make_float4(ov[0], ov[1], ov[2], ov[3]);
        *(float4*)(ksm + c * 68 + row * 8 + 4) = make_float4(ov[4], ov[5], ov[6], ov[7]);
    }
    __syncthreads();

    // ---- 1x1 projection 128 -> 64: 16 outputs/thread, split-K over 2 halves ----
    {
        float r[16];
        const int ppx   = t & 63;         // pixel
        const int pog   = (t >> 6) & 3;   // outputs pog*16..pog*16+15
        const int phalf = (t >> 8) & 1;   // cc half
        const bool pact = (t < 512);

        if (pact) {
            #pragma unroll
            for (int j = 0; j < 16; ++j)
                r[j] = phalf ? 0.f : __ldg(&b_proj[pog * 16 + j]);

            const int ccb = phalf * 64;
            #pragma unroll 4
            for (int cc = ccb; cc < ccb + 64; ++cc) {
                float ov = ksm[cc * 68 + ppx];
                const float* wr = wpT + cc * 68 + pog * 16;
                float4 w0 = *(const float4*)(wr);
                float4 w1 = *(const float4*)(wr + 4);
                float4 w2 = *(const float4*)(wr + 8);
                float4 w3 = *(const float4*)(wr + 12);
                r[0]  += ov * w0.x;  r[1]  += ov * w0.y;
                r[2]  += ov * w0.z;  r[3]  += ov * w0.w;
                r[4]  += ov * w1.x;  r[5]  += ov * w1.y;
                r[6]  += ov * w1.z;  r[7]  += ov * w1.w;
                r[8]  += ov * w2.x;  r[9]  += ov * w2.y;
                r[10] += ov * w2.z;  r[11] += ov * w2.w;
                r[12] += ov * w3.x;  r[13] += ov * w3.y;
                r[14] += ov * w3.z;  r[15] += ov * w3.w;
            }
        }

        // half-1 (t in [256,512)) writes partials [j][thread] (conflict-free)
        if (pact && phalf) {
            int s = t - 256;
            #pragma unroll
            for (int j = 0; j < 16; ++j)
                vsm[j * 256 + s] = r[j];
        }
        __syncthreads();
        if (pact && !phalf) {
            const int gy = by * 8 + (ppx >> 3);
            const int gx = bx * 8 + (ppx & 7);
            #pragma unroll
            for (int j = 0; j < 16; ++j) {
                float rv = r[j] + vsm[j * 256 + t];
                int o = pog * 16 + j;
                out[((size_t)(bb * 64 + o) * IMH + gy) * IMW + gx] = rv;
            }
        }
    }
}

extern "C" void kernel_launch(void* const* d_in, const int* in_sizes, int n_in,
                              void* d_out, int out_size) {
    const float* x        = (const float*)d_in[0];
    const float* w_hidden = (const float*)d_in[1];
    const float* b_hidden = (const float*)d_in[2];
    const float* w_dw     = (const float*)d_in[3];
    const float* b_dw     = (const float*)d_in[4];
    const float* w_proj   = (const float*)d_in[5];
    const float* b_proj   = (const float*)d_in[6];
    const float* ln_w     = (const float*)d_in[7];
    const float* ln_b     = (const float*)d_in[8];
    float* out = (float*)d_out;

    const int k1_smem = K1_SMEM * sizeof(float);   // 100352 B
    const int k2_smem = K2_SMEM * sizeof(float);   // 180992 B
    cudaFuncSetAttribute(k1_conv1x1, cudaFuncAttributeMaxDynamicSharedMemorySize, k1_smem);
    cudaFuncSetAttribute(k2_rest,    cudaFuncAttributeMaxDynamicSharedMemorySize, k2_smem);

    dim3 g1(512, 4);
    k1_conv1x1<<<g1, 1024, k1_smem>>>(x, w_hidden, b_hidden);

    dim3 g2(32, 32, 4);
    k2_rest<<<g2, 1024, k2_smem>>>(w_dw, b_dw, w_proj, b_proj, ln_w, ln_b, out);
}

// round 14
// speedup vs baseline: 1.1311x; 1.0038x over previous
#include <cuda_runtime.h>
#include <cstdint>

#define IMH 256
#define IMW 256

// 402 MB scratch for hidden = conv1x1(x) + b_hidden, NCHW [4][384][256][256]
__device__ float g_hidden[4 * 384 * 256 * 256];

// ======================= K1: 1x1 conv, whole image, no halo =======================
// 1024 thr, warp=4px broadcast / lane=4ch; weights double-buffered with
// register-staged prefetch (LDG batch before GEMM, STS after).
#define K1_SMEM (64 * 128 + 2 * 64 * 132)   // 25088 floats = 100352 B

extern __shared__ float smem[];

__global__ __launch_bounds__(1024, 1)
void k1_conv1x1(const float* __restrict__ x,
                const float* __restrict__ w_hidden,
                const float* __restrict__ b_hidden)
{
    float* xs = smem;                       // [64][128]
    float* wsbuf[2] = { smem + 8192, smem + 8192 + 8448 };

    const int t   = threadIdx.x;
    const int b   = blockIdx.y;
    const int px0 = blockIdx.x * 128;
    const int w   = t >> 5;        // warp: pixels w*4..w*4+3
    const int l   = t & 31;        // lane: channels l*4..l*4+3

    for (int idx = t; idx < 64 * 128; idx += 1024) {
        int c = idx >> 7, p = idx & 127;
        xs[idx] = x[((size_t)(b * 64 + c) << 16) + px0 + p];
    }
    for (int idx = t; idx < 64 * 128; idx += 1024) {
        int i = idx & 63, c = idx >> 6;
        wsbuf[0][i * 132 + c] = w_hidden[c * 64 + i];
    }
    __syncthreads();

    for (int pass = 0; pass < 3; ++pass) {
        const int pch = pass * 128;
        const float* ws = wsbuf[pass & 1];

        // batch next pass's weight LDGs into registers (MLP=8); latency hides
        // behind the GEMM below. STS happens after the GEMM, before the barrier.
        float wpre[8];
        if (pass < 2) {
            const float* src = w_hidden + (pch + 128) * 64;
            #pragma unroll
            for (int u = 0; u < 8; ++u) {
                int idx = t + u * 1024;
                int i = idx & 63, cch = idx >> 6;
                wpre[u] = __ldg(&src[cch * 64 + i]);
            }
        }

        float acc[4][4];
        #pragma unroll
        for (int j = 0; j < 4; ++j) {
            float bv = __ldg(&b_hidden[pch + l * 4 + j]);
            acc[j][0] = bv; acc[j][1] = bv; acc[j][2] = bv; acc[j][3] = bv;
        }
        const float* xsp = xs + w * 4;
        const float* wsp = ws + l * 4;
        #pragma unroll 4
        for (int i = 0; i < 64; ++i) {
            float4 xv = *(const float4*)(xsp + i * 128);
            float4 wv = *(const float4*)(wsp + i * 132);
            acc[0][0] += wv.x * xv.x; acc[0][1] += wv.x * xv.y;
            acc[0][2] += wv.x * xv.z; acc[0][3] += wv.x * xv.w;
            acc[1][0] += wv.y * xv.x; acc[1][1] += wv.y * xv.y;
            acc[1][2] += wv.y * xv.z; acc[1][3] += wv.y * xv.w;
            acc[2][0] += wv.z * xv.x; acc[2][1] += wv.z * xv.y;
            acc[2][2] += wv.z * xv.z; acc[2][3] += wv.z * xv.w;
            acc[3][0] += wv.w * xv.x; acc[3][1] += wv.w * xv.y;
            acc[3][2] += wv.w * xv.z; acc[3][3] += wv.w * xv.w;
        }

        if (pass < 2) {
            float* wn = wsbuf[(pass + 1) & 1];
            #pragma unroll
            for (int u = 0; u < 8; ++u) {
                int idx = t + u * 1024;
                int i = idx & 63, cch = idx >> 6;
                wn[i * 132 + cch] = wpre[u];
            }
        }

        #pragma unroll
        for (int j = 0; j < 4; ++j) {
            int c = pch + l * 4 + j;
            float4 hv = make_float4(acc[j][0], acc[j][1], acc[j][2], acc[j][3]);
            *(float4*)(g_hidden + ((size_t)(b * 384 + c) << 16) + px0 + w * 4) = hv;
        }
        __syncthreads();
    }
}

// ======================= K2: dw conv + circ-conv + LN + proj =======================
// grid (32, 32, 4): one 8x8 patch per block. 1024 threads.
#define OFF_HS   0          // hs [128][132] = 16896; wpT[128][68] overlays; hs tail = proj scratch
#define OFF_WPT  0
#define OFF_Q    16896      // [128][68]
#define OFF_K    25600      // [128][68]
#define OFF_V    34304      // [128][68]  (also proj partial scratch q1/q2)
#define OFF_PS   43008      // [16][66]
#define OFF_PQ   44064      // [16][66]
#define OFF_MEAN 45120      // [64]
#define OFF_RSTD 45184      // [64]
#define K2_SMEM  45248      // 180992 bytes

__global__ __launch_bounds__(1024, 1)
void k2_rest(const float* __restrict__ w_dw,
             const float* __restrict__ b_dw,
             const float* __restrict__ w_proj,
             const float* __restrict__ b_proj,
             const float* __restrict__ ln_w,
             const float* __restrict__ ln_b,
             float* __restrict__ out)
{
    float* hs   = smem + OFF_HS;
    float* wpT  = smem + OFF_WPT;
    float* qsm  = smem + OFF_Q;
    float* ksm  = smem + OFF_K;
    float* vsm  = smem + OFF_V;
    float* ps   = smem + OFF_PS;
    float* pq   = smem + OFF_PQ;
    float* mean_s = smem + OFF_MEAN;
    float* rstd_s = smem + OFF_RSTD;

    const int t  = threadIdx.x;
    const int bx = blockIdx.x;
    const int by = blockIdx.y;
    const int bb = blockIdx.z;
    const int gx0 = bx * 8 - 1;
    const int gy0 = by * 8 - 1;

    // conflict-free (channel, row) map: quarter-warp = 8 channels, fixed row
    const int c   = ((t >> 6) << 3) | (t & 7);   // 0..127
    const int row = (t >> 3) & 7;                // 0..7
    const int p8  = t & 63;
    const int clg = t >> 6;       // 0..15 (LN stats map)

    // ---- staging geometry: tp = t&127 same pixel for all 16 loads
    const int tp  = t & 127;
    const int cc0 = t >> 7;       // 0..7
    int sty = tp / 10, stx = tp - sty * 10;
    const int sgy = gy0 + sty, sgx = gx0 + stx;
    const bool sload = (tp < 100) && ((unsigned)sgy < IMH) && ((unsigned)sgx < IMW);
    const bool sstore = (tp < 100);
    const size_t gpix = ((size_t)sgy << 8) + sgx;
    const int hoff = sty * 12 + stx;

    // prefetch pass-0 hidden (batched independent loads -> MLP=16)
    float v[16];
    {
        const float* gbase = g_hidden + (((size_t)(bb * 384 + cc0)) << 16) + gpix;
        #pragma unroll
        for (int u = 0; u < 16; ++u)
            v[u] = sload ? __ldg(gbase + ((size_t)(8 * u) << 16)) : 0.f;
    }

    // ---- 3 passes: store staged tile + prefetch next + depthwise 3x3 ----
    for (int pass = 0; pass < 3; ++pass) {
        const int pch = pass * 128;

        __syncthreads();   // hs free (prev dw done)
        if (sstore) {
            #pragma unroll
            for (int u = 0; u < 16; ++u)
                hs[(cc0 + 8 * u) * 132 + hoff] = v[u];
        }
        __syncthreads();

        if (pass < 2) {
            const float* gbase = g_hidden + (((size_t)(bb * 384 + pch + 128 + cc0)) << 16) + gpix;
            #pragma unroll
            for (int u = 0; u < 16; ++u)
                v[u] = sload ? __ldg(gbase + ((size_t)(8 * u) << 16)) : 0.f;
        }

        float* dst = (pass == 0) ? qsm : (pass == 1) ? ksm : vsm;
        float wd9[9];
        #pragma unroll
        for (int tap = 0; tap < 9; ++tap) wd9[tap] = __ldg(&w_dw[(pch + c) * 9 + tap]);
        float bv = __ldg(&b_dw[pch + c]);
        float o8[8];
        #pragma unroll
        for (int j = 0; j < 8; ++j) o8[j] = bv;
        const float* hrow = hs + c * 132 + row * 12;
        #pragma unroll
        for (int dy = 0; dy < 3; ++dy) {
            float4 A0 = *(const float4*)(hrow + dy * 12);
            float4 A1 = *(const float4*)(hrow + dy * 12 + 4);
            float4 A2 = *(const float4*)(hrow + dy * 12 + 8);
            float rr[12] = {A0.x, A0.y, A0.z, A0.w, A1.x, A1.y, A1.z, A1.w,
                            A2.x, A2.y, A2.z, A2.w};
            float w0 = wd9[dy * 3], w1 = wd9[dy * 3 + 1], w2 = wd9[dy * 3 + 2];
            #pragma unroll
            for (int j = 0; j < 8; ++j)
                o8[j] += rr[j] * w0 + rr[j + 1] * w1 + rr[j + 2] * w2;
        }
        *(float4*)(dst + c * 68 + row * 8)     = make_float4(o8[0], o8[1], o8[2], o8[3]);
        *(float4*)(dst + c * 68 + row * 8 + 4) = make_float4(o8[4], o8[5], o8[6], o8[7]);
    }
    __syncthreads();   // dw done with hs -> overlay wpT

    // stage wpT[c][68] = w_proj[o][c]
    for (int idx = t; idx < 64 * 128; idx += 1024) {
        int cc = idx & 127, o = idx >> 7;
        wpT[cc * 68 + o] = w_proj[o * 128 + cc];
    }
    // ordered before proj by the syncs below

    // ---- Phase B: circular conv per 8x8 patch (conflict-free loads) ----
    float bacc[8];
    #pragma unroll
    for (int j = 0; j < 8; ++j) bacc[j] = 0.f;
    {
        const float* qrow = qsm + c * 68;
        const float* krow = ksm + c * 68;
        #pragma unroll
        for (int a = 0; a < 8; ++a) {
            float4 qa = *(const float4*)(qrow + a * 8);
            float4 qb = *(const float4*)(qrow + a * 8 + 4);
            float qq[8] = {qa.x, qa.y, qa.z, qa.w, qb.x, qb.y, qb.z, qb.w};
            int r0 = (row - a) & 7;
            float4 k0 = *(const float4*)(krow + r0 * 8);
            float4 k1 = *(const float4*)(krow + r0 * 8 + 4);
            float kk[8] = {k0.x, k0.y, k0.z, k0.w, k1.x, k1.y, k1.z, k1.w};
            #pragma unroll
            for (int b2 = 0; b2 < 8; ++b2) {
                #pragma unroll
                for (int j = 0; j < 8; ++j)
                    bacc[j] += qq[b2] * kk[(j - b2) & 7];
            }
        }
    }
    __syncthreads();

    // write Phase-B output to qsm (q dead) for the LN reduction
    *(float4*)(qsm + c * 68 + row * 8)     = make_float4(bacc[0], bacc[1], bacc[2], bacc[3]);
    *(float4*)(qsm + c * 68 + row * 8 + 4) = make_float4(bacc[4], bacc[5], bacc[6], bacc[7]);
    __syncthreads();

    // ---- LayerNorm stats over 128 channels per pixel ----
    {
        float s = 0.f, ss = 0.f;
        #pragma unroll
        for (int u = 0; u < 8; ++u) {
            float v2 = qsm[(clg * 8 + u) * 68 + p8];
            s += v2; ss += v2 * v2;
        }
        ps[clg * 66 + p8] = s;
        pq[clg * 66 + p8] = ss;
    }
    __syncthreads();
    if (t < 64) {
        float sm = 0.f, sq = 0.f;
        #pragma unroll
        for (int g = 0; g < 16; ++g) { sm += ps[g * 66 + t]; sq += pq[g * 66 + t]; }
        float mu  = sm * (1.f / 128.f);
        float var = sq * (1.f / 128.f) - mu * mu;
        mean_s[t] = mu;
        rstd_s[t] = rsqrtf(var + 1e-5f);
    }
    __syncthreads();

    // ---- normalize, scale/shift, multiply by v -> ksm (k dead) ----
    {
        float lw = __ldg(&ln_w[c]);
        float lb = __ldg(&ln_b[c]);
        float4 v0 = *(const float4*)(vsm + c * 68 + row * 8);
        float4 v1 = *(const float4*)(vsm + c * 68 + row * 8 + 4);
        float vv[8] = {v0.x, v0.y, v0.z, v0.w, v1.x, v1.y, v1.z, v1.w};
        float ov[8];
        #pragma unroll
        for (int j = 0; j < 8; ++j) {
            int px = row * 8 + j;
            float o = (bacc[j] - mean_s[px]) * rstd_s[px] * lw + lb;
            ov[j] = vv[j] * o;
        }
        *(float4*)(ksm + c * 68 + row * 8)     = make_float4(ov[0], ov[1], ov[2], ov[3]);
        *(float4*)(ksm + c * 68 + row * 8 + 4) = make_float4(ov[4], ov[5], ov[6], ov[7]);
    }
    __syncthreads();

    // ---- 1x1 projection 128 -> 64: all 1024 threads, 4-way split-K ----
    // thread: pixel ppx, 16 outputs pog*16.., cc quarter pq4*32..
    {
        const int ppx = t & 63;
        const int pog = (t >> 6) & 3;
        const int pq4 = t >> 8;            // 0..3
        float* scr12 = vsm;                // quarters 1,2 scratch (vsm dead)
        float* scr3  = hs + 8704;          // quarter 3 scratch (hs tail past wpT)

        float r[16];
        #pragma unroll
        for (int j = 0; j < 16; ++j)
            r[j] = (pq4 == 0) ? __ldg(&b_proj[pog * 16 + j]) : 0.f;

        const int ccb = pq4 * 32;
        #pragma unroll 4
        for (int cc = ccb; cc < ccb + 32; ++cc) {
            float ov = ksm[cc * 68 + ppx];
            const float* wr = wpT + cc * 68 + pog * 16;
            float4 w0 = *(const float4*)(wr);
            float4 w1 = *(const float4*)(wr + 4);
            float4 w2 = *(const float4*)(wr + 8);
            float4 w3 = *(const float4*)(wr + 12);
            r[0]  += ov * w0.x;  r[1]  += ov * w0.y;
            r[2]  += ov * w0.z;  r[3]  += ov * w0.w;
            r[4]  += ov * w1.x;  r[5]  += ov * w1.y;
            r[6]  += ov * w1.z;  r[7]  += ov * w1.w;
            r[8]  += ov * w2.x;  r[9]  += ov * w2.y;
            r[10] += ov * w2.z;  r[11] += ov * w2.w;
            r[12] += ov * w3.x;  r[13] += ov * w3.y;
            r[14] += ov * w3.z;  r[15] += ov * w3.w;
        }

        // quarters 1..3 write partials [j][thread] (conflict-free)
        if (pq4 == 1) {
            int s = t - 256;
            #pragma unroll
            for (int j = 0; j < 16; ++j) scr12[j * 256 + s] = r[j];
        } else if (pq4 == 2) {
            int s = t - 512;
            #pragma unroll
            for (int j = 0; j < 16; ++j) scr12[4096 + j * 256 + s] = r[j];
        } else if (pq4 == 3) {
            int s = t - 768;
            #pragma unroll
            for (int j = 0; j < 16; ++j) scr3[j * 256 + s] = r[j];
        }
        __syncthreads();
        if (pq4 == 0) {
            const int gy = by * 8 + (ppx >> 3);
            const int gx = bx * 8 + (ppx & 7);
            #pragma unroll
            for (int j = 0; j < 16; ++j) {
                float rv = r[j] + scr12[j * 256 + t] + scr12[4096 + j * 256 + t]
                                + scr3[j * 256 + t];
                int o = pog * 16 + j;
                out[((size_t)(bb * 64 + o) * IMH + gy) * IMW + gx] = rv;
            }
        }
    }
}

extern "C" void kernel_launch(void* const* d_in, const int* in_sizes, int n_in,
                              void* d_out, int out_size) {
    const float* x        = (const float*)d_in[0];
    const float* w_hidden = (const float*)d_in[1];
    const float* b_hidden = (const float*)d_in[2];
    const float* w_dw     = (const float*)d_in[3];
    const float* b_dw     = (const float*)d_in[4];
    const float* w_proj   = (const float*)d_in[5];
    const float* b_proj   = (const float*)d_in[6];
    const float* ln_w     = (const float*)d_in[7];
    const float* ln_b     = (const float*)d_in[8];
    float* out = (float*)d_out;

    const int k1_smem = K1_SMEM * sizeof(float);   // 100352 B
    const int k2_smem = K2_SMEM * sizeof(float);   // 180992 B
    cudaFuncSetAttribute(k1_conv1x1, cudaFuncAttributeMaxDynamicSharedMemorySize, k1_smem);
    cudaFuncSetAttribute(k2_rest,    cudaFuncAttributeMaxDynamicSharedMemorySize, k2_smem);

    dim3 g1(512, 4);
    k1_conv1x1<<<g1, 1024, k1_smem>>>(x, w_hidden, b_hidden);

    dim3 g2(32, 32, 4);
    k2_rest<<<g2, 1024, k2_smem>>>(w_dw, b_dw, w_proj, b_proj, ln_w, ln_b, out);
}

// round 15
// speedup vs baseline: 1.1644x; 1.0294x over previous
#include <cuda_runtime.h>
#include <cstdint>

#define IMH 256
#define IMW 256

// 402 MB scratch for hidden = conv1x1(x) + b_hidden, NCHW [4][384][256][256]
__device__ float g_hidden[4 * 384 * 256 * 256];

// ======================= K1: 1x1 conv, whole image, no halo =======================
// grid (256, 4): 256-pixel strips (2 x 128) per block; weights staged once per
// pass serve both strips. 1024 thr, warp=4px broadcast / lane=4ch, dbuf weights
// with register-staged prefetch.
#define K1_SMEM (64 * 256 + 2 * 64 * 132)   // 33280 floats = 133120 B

extern __shared__ float smem[];

__global__ __launch_bounds__(1024, 1)
void k1_conv1x1(const float* __restrict__ x,
                const float* __restrict__ w_hidden,
                const float* __restrict__ b_hidden)
{
    float* xs = smem;                         // [64][256]
    float* wsbuf[2] = { smem + 16384, smem + 16384 + 8448 };

    const int t   = threadIdx.x;
    const int b   = blockIdx.y;
    const int px0 = blockIdx.x * 256;
    const int w   = t >> 5;        // warp: pixels w*4..w*4+3 (within a strip)
    const int l   = t & 31;        // lane: channels l*4..l*4+3

    // stage x strips: xs[c][p], p in 0..255 (coalesced)
    for (int idx = t; idx < 64 * 256; idx += 1024) {
        int c = idx >> 8, p = idx & 255;
        xs[idx] = x[((size_t)(b * 64 + c) << 16) + px0 + p];
    }
    // stage pass-0 weights
    for (int idx = t; idx < 64 * 128; idx += 1024) {
        int i = idx & 63, c = idx >> 6;
        wsbuf[0][i * 132 + c] = w_hidden[c * 64 + i];
    }
    __syncthreads();

    for (int pass = 0; pass < 3; ++pass) {
        const int pch = pass * 128;
        const float* ws = wsbuf[pass & 1];

        // batch next pass's weight LDGs into registers (MLP=8)
        float wpre[8];
        if (pass < 2) {
            const float* src = w_hidden + (pch + 128) * 64;
            #pragma unroll
            for (int u = 0; u < 8; ++u) {
                int idx = t + u * 1024;
                int i = idx & 63, cch = idx >> 6;
                wpre[u] = __ldg(&src[cch * 64 + i]);
            }
        }

        float b4[4];
        #pragma unroll
        for (int j = 0; j < 4; ++j) b4[j] = __ldg(&b_hidden[pch + l * 4 + j]);

        #pragma unroll
        for (int strip = 0; strip < 2; ++strip) {
            float acc[4][4];
            #pragma unroll
            for (int j = 0; j < 4; ++j) {
                acc[j][0] = b4[j]; acc[j][1] = b4[j];
                acc[j][2] = b4[j]; acc[j][3] = b4[j];
            }
            const float* xsp = xs + strip * 128 + w * 4;
            const float* wsp = ws + l * 4;
            #pragma unroll 4
            for (int i = 0; i < 64; ++i) {
                float4 xv = *(const float4*)(xsp + i * 256);
                float4 wv = *(const float4*)(wsp + i * 132);
                acc[0][0] += wv.x * xv.x; acc[0][1] += wv.x * xv.y;
                acc[0][2] += wv.x * xv.z; acc[0][3] += wv.x * xv.w;
                acc[1][0] += wv.y * xv.x; acc[1][1] += wv.y * xv.y;
                acc[1][2] += wv.y * xv.z; acc[1][3] += wv.y * xv.w;
                acc[2][0] += wv.z * xv.x; acc[2][1] += wv.z * xv.y;
                acc[2][2] += wv.z * xv.z; acc[2][3] += wv.z * xv.w;
                acc[3][0] += wv.w * xv.x; acc[3][1] += wv.w * xv.y;
                acc[3][2] += wv.w * xv.z; acc[3][3] += wv.w * xv.w;
            }
            #pragma unroll
            for (int j = 0; j < 4; ++j) {
                int c = pch + l * 4 + j;
                float4 hv = make_float4(acc[j][0], acc[j][1], acc[j][2], acc[j][3]);
                *(float4*)(g_hidden + ((size_t)(b * 384 + c) << 16)
                           + px0 + strip * 128 + w * 4) = hv;
            }
        }

        if (pass < 2) {
            float* wn = wsbuf[(pass + 1) & 1];
            #pragma unroll
            for (int u = 0; u < 8; ++u) {
                int idx = t + u * 1024;
                int i = idx & 63, cch = idx >> 6;
                wn[i * 132 + cch] = wpre[u];
            }
        }
        __syncthreads();
    }
}

// ======================= K2: dw conv + circ-conv + LN + proj =======================
// grid (32, 32, 4): one 8x8 patch per block. 1024 threads. (R13 config, 560us verified)
#define OFF_HS   0          // hs [128][132] = 16896; wpT[128][68] overlays after passes
#define OFF_WPT  0
#define OFF_Q    16896      // [128][68]
#define OFF_K    25600      // [128][68]
#define OFF_V    34304      // [128][68]  (also proj partial scratch)
#define OFF_PS   43008      // [16][66]
#define OFF_PQ   44064      // [16][66]
#define OFF_MEAN 45120      // [64]
#define OFF_RSTD 45184      // [64]
#define K2_SMEM  45248      // 180992 bytes

__global__ __launch_bounds__(1024, 1)
void k2_rest(const float* __restrict__ w_dw,
             const float* __restrict__ b_dw,
             const float* __restrict__ w_proj,
             const float* __restrict__ b_proj,
             const float* __restrict__ ln_w,
             const float* __restrict__ ln_b,
             float* __restrict__ out)
{
    float* hs   = smem + OFF_HS;
    float* wpT  = smem + OFF_WPT;
    float* qsm  = smem + OFF_Q;
    float* ksm  = smem + OFF_K;
    float* vsm  = smem + OFF_V;
    float* ps   = smem + OFF_PS;
    float* pq   = smem + OFF_PQ;
    float* mean_s = smem + OFF_MEAN;
    float* rstd_s = smem + OFF_RSTD;

    const int t  = threadIdx.x;
    const int bx = blockIdx.x;
    const int by = blockIdx.y;
    const int bb = blockIdx.z;
    const int gx0 = bx * 8 - 1;
    const int gy0 = by * 8 - 1;

    // conflict-free (channel, row) map: quarter-warp = 8 channels, fixed row
    const int c   = ((t >> 6) << 3) | (t & 7);   // 0..127
    const int row = (t >> 3) & 7;                // 0..7
    const int p8  = t & 63;
    const int clg = t >> 6;       // 0..15 (LN stats map)

    // ---- staging geometry: tp = t&127 same pixel for all 16 loads
    const int tp  = t & 127;
    const int cc0 = t >> 7;       // 0..7
    int sty = tp / 10, stx = tp - sty * 10;
    const int sgy = gy0 + sty, sgx = gx0 + stx;
    const bool sload = (tp < 100) && ((unsigned)sgy < IMH) && ((unsigned)sgx < IMW);
    const bool sstore = (tp < 100);
    const size_t gpix = ((size_t)sgy << 8) + sgx;
    const int hoff = sty * 12 + stx;

    // prefetch pass-0 hidden (batched independent loads -> MLP=16)
    float v[16];
    {
        const float* gbase = g_hidden + (((size_t)(bb * 384 + cc0)) << 16) + gpix;
        #pragma unroll
        for (int u = 0; u < 16; ++u)
            v[u] = sload ? __ldg(gbase + ((size_t)(8 * u) << 16)) : 0.f;
    }

    // ---- 3 passes: store staged tile + prefetch next + depthwise 3x3 ----
    for (int pass = 0; pass < 3; ++pass) {
        const int pch = pass * 128;

        __syncthreads();   // hs free (prev dw done)
        if (sstore) {
            #pragma unroll
            for (int u = 0; u < 16; ++u)
                hs[(cc0 + 8 * u) * 132 + hoff] = v[u];
        }
        __syncthreads();

        if (pass < 2) {
            const float* gbase = g_hidden + (((size_t)(bb * 384 + pch + 128 + cc0)) << 16) + gpix;
            #pragma unroll
            for (int u = 0; u < 16; ++u)
                v[u] = sload ? __ldg(gbase + ((size_t)(8 * u) << 16)) : 0.f;
        }

        float* dst = (pass == 0) ? qsm : (pass == 1) ? ksm : vsm;
        float wd9[9];
        #pragma unroll
        for (int tap = 0; tap < 9; ++tap) wd9[tap] = __ldg(&w_dw[(pch + c) * 9 + tap]);
        float bv = __ldg(&b_dw[pch + c]);
        float o8[8];
        #pragma unroll
        for (int j = 0; j < 8; ++j) o8[j] = bv;
        const float* hrow = hs + c * 132 + row * 12;
        #pragma unroll
        for (int dy = 0; dy < 3; ++dy) {
            float4 A0 = *(const float4*)(hrow + dy * 12);
            float4 A1 = *(const float4*)(hrow + dy * 12 + 4);
            float4 A2 = *(const float4*)(hrow + dy * 12 + 8);
            float rr[12] = {A0.x, A0.y, A0.z, A0.w, A1.x, A1.y, A1.z, A1.w,
                            A2.x, A2.y, A2.z, A2.w};
            float w0 = wd9[dy * 3], w1 = wd9[dy * 3 + 1], w2 = wd9[dy * 3 + 2];
            #pragma unroll
            for (int j = 0; j < 8; ++j)
                o8[j] += rr[j] * w0 + rr[j + 1] * w1 + rr[j + 2] * w2;
        }
        *(float4*)(dst + c * 68 + row * 8)     = make_float4(o8[0], o8[1], o8[2], o8[3]);
        *(float4*)(dst + c * 68 + row * 8 + 4) = make_float4(o8[4], o8[5], o8[6], o8[7]);
    }
    __syncthreads();   // dw done with hs -> overlay wpT

    // stage wpT[c][68] = w_proj[o][c]
    for (int idx = t; idx < 64 * 128; idx += 1024) {
        int cc = idx & 127, o = idx >> 7;
        wpT[cc * 68 + o] = w_proj[o * 128 + cc];
    }
    // ordered before proj by the syncs below

    // ---- Phase B: circular conv per 8x8 patch (conflict-free loads) ----
    float bacc[8];
    #pragma unroll
    for (int j = 0; j < 8; ++j) bacc[j] = 0.f;
    {
        const float* qrow = qsm + c * 68;
        const float* krow = ksm + c * 68;
        #pragma unroll
        for (int a = 0; a < 8; ++a) {
            float4 qa = *(const float4*)(qrow + a * 8);
            float4 qb = *(const float4*)(qrow + a * 8 + 4);
            float qq[8] = {qa.x, qa.y, qa.z, qa.w, qb.x, qb.y, qb.z, qb.w};
            int r0 = (row - a) & 7;
            float4 k0 = *(const float4*)(krow + r0 * 8);
            float4 k1 = *(const float4*)(krow + r0 * 8 + 4);
            float kk[8] = {k0.x, k0.y, k0.z, k0.w, k1.x, k1.y, k1.z, k1.w};
            #pragma unroll
            for (int b2 = 0; b2 < 8; ++b2) {
                #pragma unroll
                for (int j = 0; j < 8; ++j)
                    bacc[j] += qq[b2] * kk[(j - b2) & 7];
            }
        }
    }
    __syncthreads();

    // write Phase-B output to qsm (q dead) for the LN reduction
    *(float4*)(qsm + c * 68 + row * 8)     = make_float4(bacc[0], bacc[1], bacc[2], bacc[3]);
    *(float4*)(qsm + c * 68 + row * 8 + 4) = make_float4(bacc[4], bacc[5], bacc[6], bacc[7]);
    __syncthreads();

    // ---- LayerNorm stats over 128 channels per pixel ----
    {
        float s = 0.f, ss = 0.f;
        #pragma unroll
        for (int u = 0; u < 8; ++u) {
            float v2 = qsm[(clg * 8 + u) * 68 + p8];
            s += v2; ss += v2 * v2;
        }
        ps[clg * 66 + p8] = s;
        pq[clg * 66 + p8] = ss;
    }
    __syncthreads();
    if (t < 64) {
        float sm = 0.f, sq = 0.f;
        #pragma unroll
        for (int g = 0; g < 16; ++g) { sm += ps[g * 66 + t]; sq += pq[g * 66 + t]; }
        float mu  = sm * (1.f / 128.f);
        float var = sq * (1.f / 128.f) - mu * mu;
        mean_s[t] = mu;
        rstd_s[t] = rsqrtf(var + 1e-5f);
    }
    __syncthreads();

    // ---- normalize, scale/shift, multiply by v -> ksm (k dead) ----
    {
        float lw = __ldg(&ln_w[c]);
        float lb = __ldg(&ln_b[c]);
        float4 v0 = *(const float4*)(vsm + c * 68 + row * 8);
        float4 v1 = *(const float4*)(vsm + c * 68 + row * 8 + 4);
        float vv[8] = {v0.x, v0.y, v0.z, v0.w, v1.x, v1.y, v1.z, v1.w};
        float ov[8];
        #pragma unroll
        for (int j = 0; j < 8; ++j) {
            int px = row * 8 + j;
            float o = (bacc[j] - mean_s[px]) * rstd_s[px] * lw + lb;
            ov[j] = vv[j] * o;
        }
        *(float4*)(ksm + c * 68 + row * 8)     = make_float4(ov[0], ov[1], ov[2], ov[3]);
        *(float4*)(ksm + c * 68 + row * 8 + 4) = make_float4(ov[4], ov[5], ov[6], ov[7]);
    }
    __syncthreads();

    // ---- 1x1 projection 128 -> 64: 16 outputs/thread, split-K over 2 halves ----
    {
        float r[16];
        const int ppx   = t & 63;         // pixel
        const int pog   = (t >> 6) & 3;   // outputs pog*16..pog*16+15
        const int phalf = (t >> 8) & 1;   // cc half
        const bool pact = (t < 512);

        if (pact) {
            #pragma unroll
            for (int j = 0; j < 16; ++j)
                r[j] = phalf ? 0.f : __ldg(&b_proj[pog * 16 + j]);

            const int ccb = phalf * 64;
            #pragma unroll 4
            for (int cc = ccb; cc < ccb + 64; ++cc) {
                float ov = ksm[cc * 68 + ppx];
                const float* wr = wpT + cc * 68 + pog * 16;
                float4 w0 = *(const float4*)(wr);
                float4 w1 = *(const float4*)(wr + 4);
                float4 w2 = *(const float4*)(wr + 8);
                float4 w3 = *(const float4*)(wr + 12);
                r[0]  += ov * w0.x;  r[1]  += ov * w0.y;
                r[2]  += ov * w0.z;  r[3]  += ov * w0.w;
                r[4]  += ov * w1.x;  r[5]  += ov * w1.y;
                r[6]  += ov * w1.z;  r[7]  += ov * w1.w;
                r[8]  += ov * w2.x;  r[9]  += ov * w2.y;
                r[10] += ov * w2.z;  r[11] += ov * w2.w;
                r[12] += ov * w3.x;  r[13] += ov * w3.y;
                r[14] += ov * w3.z;  r[15] += ov * w3.w;
            }
        }

        // half-1 (t in [256,512)) writes partials [j][thread] (conflict-free)
        if (pact && phalf) {
            int s = t - 256;
            #pragma unroll
            for (int j = 0; j < 16; ++j)
                vsm[j * 256 + s] = r[j];
        }
        __syncthreads();
        if (pact && !phalf) {
            const int gy = by * 8 + (ppx >> 3);
            const int gx = bx * 8 + (ppx & 7);
            #pragma unroll
            for (int j = 0; j < 16; ++j) {
                float rv = r[j] + vsm[j * 256 + t];
                int o = pog * 16 + j;
                out[((size_t)(bb * 64 + o) * IMH + gy) * IMW + gx] = rv;
            }
        }
    }
}

extern "C" void kernel_launch(void* const* d_in, const int* in_sizes, int n_in,
                              void* d_out, int out_size) {
    const float* x        = (const float*)d_in[0];
    const float* w_hidden = (const float*)d_in[1];
    const float* b_hidden = (const float*)d_in[2];
    const float* w_dw     = (const float*)d_in[3];
    const float* b_dw     = (const float*)d_in[4];
    const float* w_proj   = (const float*)d_in[5];
    const float* b_proj   = (const float*)d_in[6];
    const float* ln_w     = (const float*)d_in[7];
    const float* ln_b     = (const float*)d_in[8];
    float* out = (float*)d_out;

    const int k1_smem = K1_SMEM * sizeof(float);   // 133120 B
    const int k2_smem = K2_SMEM * sizeof(float);   // 180992 B
    cudaFuncSetAttribute(k1_conv1x1, cudaFuncAttributeMaxDynamicSharedMemorySize, k1_smem);
    cudaFuncSetAttribute(k2_rest,    cudaFuncAttributeMaxDynamicSharedMemorySize, k2_smem);

    dim3 g1(256, 4);
    k1_conv1x1<<<g1, 1024, k1_smem>>>(x, w_hidden, b_hidden);

    dim3 g2(32, 32, 4);
    k2_rest<<<g2, 1024, k2_smem>>>(w_dw, b_dw, w_proj, b_proj, ln_w, ln_b, out);
}

// round 16
// speedup vs baseline: 1.2054x; 1.0352x over previous
#include <cuda_runtime.h>
#include <cstdint>

#define IMH 256
#define IMW 256

// 402 MB scratch for hidden = conv1x1(x) + b_hidden, NCHW [4][384][256][256]
__device__ float g_hidden[4 * 384 * 256 * 256];

// ======================= K1: 1x1 conv, whole image, no halo =======================
// grid (256, 4): 256-pixel strips (2 x 128) per block; weights staged once per
// pass serve both strips. 1024 thr, warp=4px broadcast / lane=4ch, dbuf weights
// with register-staged prefetch. (R15 verified, unchanged)
#define K1_SMEM (64 * 256 + 2 * 64 * 132)   // 33280 floats = 133120 B

extern __shared__ float smem[];

__global__ __launch_bounds__(1024, 1)
void k1_conv1x1(const float* __restrict__ x,
                const float* __restrict__ w_hidden,
                const float* __restrict__ b_hidden)
{
    float* xs = smem;                         // [64][256]
    float* wsbuf[2] = { smem + 16384, smem + 16384 + 8448 };

    const int t   = threadIdx.x;
    const int b   = blockIdx.y;
    const int px0 = blockIdx.x * 256;
    const int w   = t >> 5;        // warp: pixels w*4..w*4+3 (within a strip)
    const int l   = t & 31;        // lane: channels l*4..l*4+3

    for (int idx = t; idx < 64 * 256; idx += 1024) {
        int c = idx >> 8, p = idx & 255;
        xs[idx] = x[((size_t)(b * 64 + c) << 16) + px0 + p];
    }
    for (int idx = t; idx < 64 * 128; idx += 1024) {
        int i = idx & 63, c = idx >> 6;
        wsbuf[0][i * 132 + c] = w_hidden[c * 64 + i];
    }
    __syncthreads();

    for (int pass = 0; pass < 3; ++pass) {
        const int pch = pass * 128;
        const float* ws = wsbuf[pass & 1];

        float wpre[8];
        if (pass < 2) {
            const float* src = w_hidden + (pch + 128) * 64;
            #pragma unroll
            for (int u = 0; u < 8; ++u) {
                int idx = t + u * 1024;
                int i = idx & 63, cch = idx >> 6;
                wpre[u] = __ldg(&src[cch * 64 + i]);
            }
        }

        float b4[4];
        #pragma unroll
        for (int j = 0; j < 4; ++j) b4[j] = __ldg(&b_hidden[pch + l * 4 + j]);

        #pragma unroll
        for (int strip = 0; strip < 2; ++strip) {
            float acc[4][4];
            #pragma unroll
            for (int j = 0; j < 4; ++j) {
                acc[j][0] = b4[j]; acc[j][1] = b4[j];
                acc[j][2] = b4[j]; acc[j][3] = b4[j];
            }
            const float* xsp = xs + strip * 128 + w * 4;
            const float* wsp = ws + l * 4;
            #pragma unroll 4
            for (int i = 0; i < 64; ++i) {
                float4 xv = *(const float4*)(xsp + i * 256);
                float4 wv = *(const float4*)(wsp + i * 132);
                acc[0][0] += wv.x * xv.x; acc[0][1] += wv.x * xv.y;
                acc[0][2] += wv.x * xv.z; acc[0][3] += wv.x * xv.w;
                acc[1][0] += wv.y * xv.x; acc[1][1] += wv.y * xv.y;
                acc[1][2] += wv.y * xv.z; acc[1][3] += wv.y * xv.w;
                acc[2][0] += wv.z * xv.x; acc[2][1] += wv.z * xv.y;
                acc[2][2] += wv.z * xv.z; acc[2][3] += wv.z * xv.w;
                acc[3][0] += wv.w * xv.x; acc[3][1] += wv.w * xv.y;
                acc[3][2] += wv.w * xv.z; acc[3][3] += wv.w * xv.w;
            }
            #pragma unroll
            for (int j = 0; j < 4; ++j) {
                int c = pch + l * 4 + j;
                float4 hv = make_float4(acc[j][0], acc[j][1], acc[j][2], acc[j][3]);
                *(float4*)(g_hidden + ((size_t)(b * 384 + c) << 16)
                           + px0 + strip * 128 + w * 4) = hv;
            }
        }

        if (pass < 2) {
            float* wn = wsbuf[(pass + 1) & 1];
            #pragma unroll
            for (int u = 0; u < 8; ++u) {
                int idx = t + u * 1024;
                int i = idx & 63, cch = idx >> 6;
                wn[i * 132 + cch] = wpre[u];
            }
        }
        __syncthreads();
    }
}

// ======================= K2: dw conv + circ-conv + LN + proj =======================
// grid (32, 32, 4): one 8x8 patch per block. 1024 threads.
#define OFF_HS   0          // hs [128][132] = 16896; wpT[128][68] overlays after passes
#define OFF_WPT  0
#define OFF_Q    16896      // [128][68]
#define OFF_K    25600      // [128][68]
#define OFF_V    34304      // [128][68]  (also proj partial scratch, 4096 floats)
#define OFF_PS   43008      // [16][66]
#define OFF_PQ   44064      // [16][66]
#define OFF_MEAN 45120      // [64]
#define OFF_RSTD 45184      // [64]
#define K2_SMEM  45248      // 180992 bytes

__global__ __launch_bounds__(1024, 1)
void k2_rest(const float* __restrict__ w_dw,
             const float* __restrict__ b_dw,
             const float* __restrict__ w_proj,
             const float* __restrict__ b_proj,
             const float* __restrict__ ln_w,
             const float* __restrict__ ln_b,
             float* __restrict__ out)
{
    float* hs   = smem + OFF_HS;
    float* wpT  = smem + OFF_WPT;
    float* qsm  = smem + OFF_Q;
    float* ksm  = smem + OFF_K;
    float* vsm  = smem + OFF_V;
    float* ps   = smem + OFF_PS;
    float* pq   = smem + OFF_PQ;
    float* mean_s = smem + OFF_MEAN;
    float* rstd_s = smem + OFF_RSTD;

    const int t  = threadIdx.x;
    const int bx = blockIdx.x;
    const int by = blockIdx.y;
    const int bb = blockIdx.z;
    const int gx0 = bx * 8 - 1;
    const int gy0 = by * 8 - 1;

    // conflict-free (channel, row) map: quarter-warp = 8 channels, fixed row
    const int c   = ((t >> 6) << 3) | (t & 7);   // 0..127
    const int row = (t >> 3) & 7;                // 0..7
    const int p8  = t & 63;
    const int clg = t >> 6;       // 0..15 (LN stats map)

    // ---- staging geometry: tp = t&127 same pixel for all 16 loads
    const int tp  = t & 127;
    const int cc0 = t >> 7;       // 0..7
    int sty = tp / 10, stx = tp - sty * 10;
    const int sgy = gy0 + sty, sgx = gx0 + stx;
    const bool sload = (tp < 100) && ((unsigned)sgy < IMH) && ((unsigned)sgx < IMW);
    const bool sstore = (tp < 100);
    const size_t gpix = ((size_t)sgy << 8) + sgx;
    const int hoff = sty * 12 + stx;

    // prefetch pass-0 hidden (batched independent loads -> MLP=16)
    float v[16];
    {
        const float* gbase = g_hidden + (((size_t)(bb * 384 + cc0)) << 16) + gpix;
        #pragma unroll
        for (int u = 0; u < 16; ++u)
            v[u] = sload ? __ldg(gbase + ((size_t)(8 * u) << 16)) : 0.f;
    }

    // ---- 3 passes: store staged tile + prefetch next + depthwise 3x3 ----
    for (int pass = 0; pass < 3; ++pass) {
        const int pch = pass * 128;

        __syncthreads();   // hs free (prev dw done)
        if (sstore) {
            #pragma unroll
            for (int u = 0; u < 16; ++u)
                hs[(cc0 + 8 * u) * 132 + hoff] = v[u];
        }
        __syncthreads();

        if (pass < 2) {
            const float* gbase = g_hidden + (((size_t)(bb * 384 + pch + 128 + cc0)) << 16) + gpix;
            #pragma unroll
            for (int u = 0; u < 16; ++u)
                v[u] = sload ? __ldg(gbase + ((size_t)(8 * u) << 16)) : 0.f;
        }

        float* dst = (pass == 0) ? qsm : (pass == 1) ? ksm : vsm;
        float wd9[9];
        #pragma unroll
        for (int tap = 0; tap < 9; ++tap) wd9[tap] = __ldg(&w_dw[(pch + c) * 9 + tap]);
        float bv = __ldg(&b_dw[pch + c]);
        float o8[8];
        #pragma unroll
        for (int j = 0; j < 8; ++j) o8[j] = bv;
        const float* hrow = hs + c * 132 + row * 12;
        #pragma unroll
        for (int dy = 0; dy < 3; ++dy) {
            float4 A0 = *(const float4*)(hrow + dy * 12);
            float4 A1 = *(const float4*)(hrow + dy * 12 + 4);
            float4 A2 = *(const float4*)(hrow + dy * 12 + 8);
            float rr[12] = {A0.x, A0.y, A0.z, A0.w, A1.x, A1.y, A1.z, A1.w,
                            A2.x, A2.y, A2.z, A2.w};
            float w0 = wd9[dy * 3], w1 = wd9[dy * 3 + 1], w2 = wd9[dy * 3 + 2];
            #pragma unroll
            for (int j = 0; j < 8; ++j)
                o8[j] += rr[j] * w0 + rr[j + 1] * w1 + rr[j + 2] * w2;
        }
        *(float4*)(dst + c * 68 + row * 8)     = make_float4(o8[0], o8[1], o8[2], o8[3]);
        *(float4*)(dst + c * 68 + row * 8 + 4) = make_float4(o8[4], o8[5], o8[6], o8[7]);
    }
    __syncthreads();   // dw done with hs -> overlay wpT

    // stage wpT[c][68] = w_proj[o][c]
    for (int idx = t; idx < 64 * 128; idx += 1024) {
        int cc = idx & 127, o = idx >> 7;
        wpT[cc * 68 + o] = w_proj[o * 128 + cc];
    }
    // ordered before proj by the syncs below

    // ---- Phase B: circular conv per 8x8 patch (conflict-free loads) ----
    float bacc[8];
    #pragma unroll
    for (int j = 0; j < 8; ++j) bacc[j] = 0.f;
    {
        const float* qrow = qsm + c * 68;
        const float* krow = ksm + c * 68;
        #pragma unroll
        for (int a = 0; a < 8; ++a) {
            float4 qa = *(const float4*)(qrow + a * 8);
            float4 qb = *(const float4*)(qrow + a * 8 + 4);
            float qq[8] = {qa.x, qa.y, qa.z, qa.w, qb.x, qb.y, qb.z, qb.w};
            int r0 = (row - a) & 7;
            float4 k0 = *(const float4*)(krow + r0 * 8);
            float4 k1 = *(const float4*)(krow + r0 * 8 + 4);
            float kk[8] = {k0.x, k0.y, k0.z, k0.w, k1.x, k1.y, k1.z, k1.w};
            #pragma unroll
            for (int b2 = 0; b2 < 8; ++b2) {
                #pragma unroll
                for (int j = 0; j < 8; ++j)
                    bacc[j] += qq[b2] * kk[(j - b2) & 7];
            }
        }
    }
    __syncthreads();

    // write Phase-B output to qsm (q dead) for the LN reduction
    *(float4*)(qsm + c * 68 + row * 8)     = make_float4(bacc[0], bacc[1], bacc[2], bacc[3]);
    *(float4*)(qsm + c * 68 + row * 8 + 4) = make_float4(bacc[4], bacc[5], bacc[6], bacc[7]);
    __syncthreads();

    // ---- LayerNorm stats over 128 channels per pixel ----
    {
        float s = 0.f, ss = 0.f;
        #pragma unroll
        for (int u = 0; u < 8; ++u) {
            float v2 = qsm[(clg * 8 + u) * 68 + p8];
            s += v2; ss += v2 * v2;
        }
        ps[clg * 66 + p8] = s;
        pq[clg * 66 + p8] = ss;
    }
    __syncthreads();
    if (t < 64) {
        float sm = 0.f, sq = 0.f;
        #pragma unroll
        for (int g = 0; g < 16; ++g) { sm += ps[g * 66 + t]; sq += pq[g * 66 + t]; }
        float mu  = sm * (1.f / 128.f);
        float var = sq * (1.f / 128.f) - mu * mu;
        mean_s[t] = mu;
        rstd_s[t] = rsqrtf(var + 1e-5f);
    }
    __syncthreads();

    // ---- normalize, scale/shift, multiply by v -> ksm (k dead) ----
    {
        float lw = __ldg(&ln_w[c]);
        float lb = __ldg(&ln_b[c]);
        float4 v0 = *(const float4*)(vsm + c * 68 + row * 8);
        float4 v1 = *(const float4*)(vsm + c * 68 + row * 8 + 4);
        float vv[8] = {v0.x, v0.y, v0.z, v0.w, v1.x, v1.y, v1.z, v1.w};
        float ov[8];
        #pragma unroll
        for (int j = 0; j < 8; ++j) {
            int px = row * 8 + j;
            float o = (bacc[j] - mean_s[px]) * rstd_s[px] * lw + lb;
            ov[j] = vv[j] * o;
        }
        *(float4*)(ksm + c * 68 + row * 8)     = make_float4(ov[0], ov[1], ov[2], ov[3]);
        *(float4*)(ksm + c * 68 + row * 8 + 4) = make_float4(ov[4], ov[5], ov[6], ov[7]);
    }
    __syncthreads();

    // ---- 1x1 projection 128 -> 64: 2 pixels/thread, 16 outputs, 2-way split-K ----
    // 256 active threads: pp = t&31 (pixels pp and pp+32), pog = (t>>5)&3,
    // phalf = (t>>7)&1. One px-set -> each (out,cc) weight broadcast loaded once
    // per (pog, phalf) warp instead of twice.
    {
        const int pp    = t & 31;
        const int pog   = (t >> 5) & 3;
        const int phalf = (t >> 7) & 1;
        const bool pact = (t < 256);

        float r0[16], r1[16];
        if (pact) {
            #pragma unroll
            for (int j = 0; j < 16; ++j) {
                float bj = phalf ? 0.f : __ldg(&b_proj[pog * 16 + j]);
                r0[j] = bj; r1[j] = bj;
            }
            const int ccb = phalf * 64;
            #pragma unroll 4
            for (int cc = ccb; cc < ccb + 64; ++cc) {
                float ova = ksm[cc * 68 + pp];
                float ovb = ksm[cc * 68 + pp + 32];
                const float* wr = wpT + cc * 68 + pog * 16;
                float4 w0 = *(const float4*)(wr);
                float4 w1 = *(const float4*)(wr + 4);
                float4 w2 = *(const float4*)(wr + 8);
                float4 w3 = *(const float4*)(wr + 12);
                float wv[16] = {w0.x, w0.y, w0.z, w0.w, w1.x, w1.y, w1.z, w1.w,
                                w2.x, w2.y, w2.z, w2.w, w3.x, w3.y, w3.z, w3.w};
                #pragma unroll
                for (int j = 0; j < 16; ++j) {
                    r0[j] += ova * wv[j];
                    r1[j] += ovb * wv[j];
                }
            }
        }

        // half-1 (t in [128,256)) writes partials [j][thread] (conflict-free)
        if (pact && phalf) {
            int s = t - 128;   // 0..127
            #pragma unroll
            for (int j = 0; j < 16; ++j) {
                vsm[j * 128 + s]          = r0[j];
                vsm[(16 + j) * 128 + s]   = r1[j];
            }
        }
        __syncthreads();
        if (pact && !phalf) {
            const int gy0p = by * 8 + (pp >> 3);
            const int gx0p = bx * 8 + (pp & 7);
            const int gy1p = gy0p + 4;       // pp+32 -> row +4, same column
            #pragma unroll
            for (int j = 0; j < 16; ++j) {
                float ra = r0[j] + vsm[j * 128 + t];
                float rb = r1[j] + vsm[(16 + j) * 128 + t];
                int o = pog * 16 + j;
                out[((size_t)(bb * 64 + o) * IMH + gy0p) * IMW + gx0p] = ra;
                out[((size_t)(bb * 64 + o) * IMH + gy1p) * IMW + gx0p] = rb;
            }
        }
    }
}

extern "C" void kernel_launch(void* const* d_in, const int* in_sizes, int n_in,
                              void* d_out, int out_size) {
    const float* x        = (const float*)d_in[0];
    const float* w_hidden = (const float*)d_in[1];
    const float* b_hidden = (const float*)d_in[2];
    const float* w_dw     = (const float*)d_in[3];
    const float* b_dw     = (const float*)d_in[4];
    const float* w_proj   = (const float*)d_in[5];
    const float* b_proj   = (const float*)d_in[6];
    const float* ln_w     = (const float*)d_in[7];
    const float* ln_b     = (const float*)d_in[8];
    float* out = (float*)d_out;

    const int k1_smem = K1_SMEM * sizeof(float);   // 133120 B
    const int k2_smem = K2_SMEM * sizeof(float);   // 180992 B
    cudaFuncSetAttribute(k1_conv1x1, cudaFuncAttributeMaxDynamicSharedMemorySize, k1_smem);
    cudaFuncSetAttribute(k2_rest,    cudaFuncAttributeMaxDynamicSharedMemorySize, k2_smem);

    dim3 g1(256, 4);
    k1_conv1x1<<<g1, 1024, k1_smem>>>(x, w_hidden, b_hidden);

    dim3 g2(32, 32, 4);
    k2_rest<<<g2, 1024, k2_smem>>>(w_dw, b_dw, w_proj, b_proj, ln_w, ln_b, out);
}